// round 2
// baseline (speedup 1.0000x reference)
#include <cuda_runtime.h>
#include <cstdint>
#include <cstddef>
#include <cub/cub.cuh>

// Problem shape (fixed by the reference setup_inputs): B=4, H=16, L=1024, D=64
constexpr int Bc = 4;
constexpr int Hc = 16;
constexpr int Lc = 1024;
constexpr int Dc = 64;

constexpr int THREADS = 256;
constexpr int IPT = 4;          // items per thread: 256*4 = 1024 = L

// One block per (b*H+h, d) pair. Sorts the q column and k column of that dim
// (key = value, payload = original sequence index), pairs equal ranks, and
// scatter-adds exp(-(dq)^2)/D into out[bh, qi, kj] where the mask is false.
// NOTE: mask arrives as int32 (harness materializes bool as int32).
__global__ __launch_bounds__(THREADS)
void sort_scatter_kernel(const float* __restrict__ q,
                         const float* __restrict__ k,
                         const int* __restrict__ mask,
                         float* __restrict__ out)
{
    using BlockSort = cub::BlockRadixSort<float, THREADS, IPT, int>;

    __shared__ typename BlockSort::TempStorage sort_ts;
    __shared__ float qs_val[Lc];
    __shared__ int   qs_idx[Lc];

    const int bid = blockIdx.x;
    const int d   = bid & (Dc - 1);
    const int bh  = bid >> 6;            // Dc == 64

    const float* qcol = q + (size_t)bh * Lc * Dc + d;
    const float* kcol = k + (size_t)bh * Lc * Dc + d;

    const int t = threadIdx.x;

    float keys[IPT];
    int   vals[IPT];

    // ---- sort q column (value, original row) ----
#pragma unroll
    for (int i = 0; i < IPT; i++) {
        int r = t * IPT + i;
        keys[i] = qcol[(size_t)r * Dc];
        vals[i] = r;
    }
    BlockSort(sort_ts).Sort(keys, vals);

    // stash sorted q in shared (rank-indexed)
#pragma unroll
    for (int i = 0; i < IPT; i++) {
        int r = t * IPT + i;
        qs_val[r] = keys[i];
        qs_idx[r] = vals[i];
    }
    __syncthreads();   // also guards temp-storage reuse between the two sorts

    // ---- sort k column ----
#pragma unroll
    for (int i = 0; i < IPT; i++) {
        int r = t * IPT + i;
        keys[i] = kcol[(size_t)r * Dc];
        vals[i] = r;
    }
    BlockSort(sort_ts).Sort(keys, vals);

    // ---- pair equal ranks, scatter-add with inline mask check ----
    const int* mrow = mask + (size_t)bh * Lc * Lc;
    float* orow = out + (size_t)bh * Lc * Lc;

    constexpr float inv_D = 1.0f / (float)Dc;

#pragma unroll
    for (int i = 0; i < IPT; i++) {
        int r = t * IPT + i;
        float dqk  = qs_val[r] - keys[i];
        float v    = __expf(-dqk * dqk) * inv_D;
        int   qi   = qs_idx[r];
        int   kj   = vals[i];
        size_t off = (size_t)qi * Lc + kj;
        if (mrow[off] == 0) {
            atomicAdd(orow + off, v);   // no return use -> REDG
        }
    }
}

extern "C" void kernel_launch(void* const* d_in, const int* in_sizes, int n_in,
                              void* d_out, int out_size)
{
    const float* q    = (const float*)d_in[0];
    const float* k    = (const float*)d_in[1];
    const int*   mask = (const int*)d_in[2];
    float*       out  = (float*)d_out;

    // Zero the whole output (only ~6% of cells get scatter hits; masked cells
    // must read 0). Graph-capturable async memset on the capture stream.
    cudaMemsetAsync(out, 0, (size_t)out_size * sizeof(float));

    sort_scatter_kernel<<<Bc * Hc * Dc, THREADS>>>(q, k, mask, out);
}